// round 13
// baseline (speedup 1.0000x reference)
#include <cuda_runtime.h>
#include <cstdint>

#define D      512
#define BATCH  256
#define TOPK   2
#define NEXP   16
#define NPAIR  (BATCH * TOPK)
#define MAXCH  32          // worst-case sum ceil(M_e/32) over 16 experts = 31
#define ROWS_C 32          // rows per chunk
#define NKS    2           // k-splits
#define KSL    (D / NKS)   // 256 kk per split
#define XS_STRIDE 36       // 32 data + 4 pad floats; 144B rows, 16B-aligned

// ---------------- scratch (per-split partial buffers) ----------------
__device__ float g_iv[NKS * NPAIR * D];
__device__ float g_ov[NKS * NPAIR * D];
__device__ float g_dv[NKS * NPAIR * D];
__device__ float g_bv[NKS * NPAIR * D];
__device__ int   g_list_w[NPAIR];
__device__ int   g_list_b[NPAIR];
__device__ int   g_chunks_w[MAXCH];   // packed: start | e<<16 | rows<<24
__device__ int   g_chunks_b[MAXCH];
__device__ int   g_nch_w, g_nch_b;

// ---------------- kernel 0: counting sort + 32-row chunk work-list ----------------
__global__ void sort_kernel(const int* __restrict__ widx, const int* __restrict__ bidx) {
    __shared__ int cw[NEXP], cb[NEXP], offw[NEXP + 1], offb[NEXP + 1], pw[NEXP], pb[NEXP];
    int t = threadIdx.x;                       // 512 threads == pair id
    if (t < NEXP) { cw[t] = 0; cb[t] = 0; }
    __syncthreads();
    int ew = widx[t];
    int eb = bidx[t];
    atomicAdd(&cw[ew], 1);
    atomicAdd(&cb[eb], 1);
    __syncthreads();
    if (t == 0) {
        int s = 0;
        for (int e = 0; e < NEXP; e++) { offw[e] = s; s += cw[e]; }
        offw[NEXP] = s;
        int n = 0;
        for (int e = 0; e < NEXP; e++)
            for (int c = offw[e]; c < offw[e + 1]; c += ROWS_C) {
                int rows = min(ROWS_C, offw[e + 1] - c);
                g_chunks_w[n++] = c | (e << 16) | (rows << 24);
            }
        g_nch_w = n;
    }
    if (t == 32) {
        int s = 0;
        for (int e = 0; e < NEXP; e++) { offb[e] = s; s += cb[e]; }
        offb[NEXP] = s;
        int n = 0;
        for (int e = 0; e < NEXP; e++)
            for (int c = offb[e]; c < offb[e + 1]; c += ROWS_C) {
                int rows = min(ROWS_C, offb[e + 1] - c);
                g_chunks_b[n++] = c | (e << 16) | (rows << 24);
            }
        g_nch_b = n;
    }
    __syncthreads();
    if (t < NEXP) { pw[t] = offw[t]; pb[t] = offb[t]; }
    __syncthreads();
    int posw = atomicAdd(&pw[ew], 1);
    g_list_w[posw] = t;
    int posb = atomicAdd(&pb[eb], 1);
    g_list_b[posb] = t;
}

// ---------------- packed f32x2 helpers ----------------
__device__ __forceinline__ uint64_t dupf2(float w) {
    uint64_t r;
    asm("mov.b64 %0, {%1, %1};" : "=l"(r) : "r"(__float_as_uint(w)));
    return r;
}
__device__ __forceinline__ void fma2(uint64_t& acc, uint64_t a, uint64_t b) {
    asm("fma.rn.f32x2 %0, %1, %2, %0;" : "+l"(acc) : "l"(a), "l"(b));
}

// ---------------- kernel 1: grouped GEMM, 32-row chunks + split-K=2 ----------------
// grid = (4 col-tiles of 128, MAXCH chunks, 4 banks * 2 ksplits), block = 128.
// Thread owns 1 column and 32 rows as 16 packed f32x2 accs. Each expert's W is
// streamed once per 32-row chunk (half the traffic of 16-row chunks); split-K
// doubles the block count for latency cover without adding W traffic.
// Per kk: 1 LDG (W) + 8 LDS.128 (broadcast) + 1 pack + 16 FFMA2; unroll 8.
__global__ __launch_bounds__(128) void gemm_kernel(
    const float* __restrict__ x,
    const float* __restrict__ iw, const float* __restrict__ ow,
    const float* __restrict__ dw, const float* __restrict__ bb) {

    int z    = blockIdx.z;
    int bank = z & 3;
    int ks   = z >> 2;
    int koff = ks * KSL;
    bool isW = bank < 3;
    int nch = isW ? g_nch_w : g_nch_b;
    if ((int)blockIdx.y >= nch) return;

    __shared__ __align__(16) float xs[KSL * XS_STRIDE];   // 36KB

    int packed = (isW ? g_chunks_w : g_chunks_b)[blockIdx.y];
    int s    = packed & 0xFFFF;
    int e    = (packed >> 16) & 0xFF;
    int rows = (packed >> 24) & 0xFF;

    const int* list = isW ? g_list_w : g_list_b;
    const float* W  = ((bank == 0) ? iw : (bank == 1) ? ow : (bank == 2) ? dw : bb)
                      + (size_t)e * D * D;
    float* out = ((bank == 0) ? g_iv : (bank == 1) ? g_ov : (bank == 2) ? g_dv : g_bv)
                 + (size_t)ks * NPAIR * D;

    int t   = threadIdx.x;
    int col = blockIdx.x * 128 + t;

    // fill transposed x sub-chunk [32 rows x 256 kk] (coalesced LDG; zero-pad)
    for (int idx2 = t; idx2 < ROWS_C * KSL; idx2 += 128) {
        int m  = idx2 >> 8;
        int kk = idx2 & (KSL - 1);
        float val = 0.0f;
        if (m < rows) val = x[(list[s + m] >> 1) * D + koff + kk];
        xs[kk * XS_STRIDE + m] = val;
    }
    __syncthreads();

    uint64_t acc[16];
#pragma unroll
    for (int j = 0; j < 16; j++) acc[j] = 0ull;

    const float* Wc = W + (size_t)koff * D + col;
#pragma unroll 8
    for (int kk = 0; kk < KSL; kk++) {
        float w = Wc[kk * D];
        uint64_t ww = dupf2(w);
        const ulonglong2* row = (const ulonglong2*)&xs[kk * XS_STRIDE];
        ulonglong2 r0 = row[0];
        ulonglong2 r1 = row[1];
        ulonglong2 r2 = row[2];
        ulonglong2 r3 = row[3];
        fma2(acc[0],  r0.x, ww);
        fma2(acc[1],  r0.y, ww);
        fma2(acc[2],  r1.x, ww);
        fma2(acc[3],  r1.y, ww);
        fma2(acc[4],  r2.x, ww);
        fma2(acc[5],  r2.y, ww);
        fma2(acc[6],  r3.x, ww);
        fma2(acc[7],  r3.y, ww);
        ulonglong2 r4 = row[4];
        ulonglong2 r5 = row[5];
        ulonglong2 r6 = row[6];
        ulonglong2 r7 = row[7];
        fma2(acc[8],  r4.x, ww);
        fma2(acc[9],  r4.y, ww);
        fma2(acc[10], r5.x, ww);
        fma2(acc[11], r5.y, ww);
        fma2(acc[12], r6.x, ww);
        fma2(acc[13], r6.y, ww);
        fma2(acc[14], r7.x, ww);
        fma2(acc[15], r7.y, ww);
    }

#pragma unroll
    for (int j = 0; j < 16; j++) {
        float2 f2 = *reinterpret_cast<float2*>(&acc[j]);
        int r = 2 * j;
        if (r < rows)     out[(size_t)list[s + r] * D + col]     = f2.x;
        if (r + 1 < rows) out[(size_t)list[s + r + 1] * D + col] = f2.y;
    }
}

// ---------------- kernel 2: sum 2 k-splits + rank-2 mix + analytic LN + bmix ------
// r5-proven 128-row-tile body; only change is summing the NKS=2 partial buffers.
__global__ __launch_bounds__(128) void mix_ln_kernel(
    const float* __restrict__ wp, const float* __restrict__ bp,
    float* __restrict__ outp) {

    int b  = blockIdx.y;
    int r0 = blockIdx.x * 128;
    int t  = threadIdx.x;

    __shared__ float u[D], v[D];
    __shared__ __align__(16) float4 sparams[128];   // {pr, qr, c, gr}
    __shared__ float red[4][5];

    float4 u4, v4;
    {
        const float* b0 = g_ov;
        const float* b1 = g_ov + (size_t)NPAIR * D;
        float4 a0 = ((const float4*)(b0 + (size_t)(2 * b) * D))[t];
        float4 a1 = ((const float4*)(b1 + (size_t)(2 * b) * D))[t];
        float4 c0 = ((const float4*)(b0 + (size_t)(2 * b + 1) * D))[t];
        float4 c1 = ((const float4*)(b1 + (size_t)(2 * b + 1) * D))[t];
        u4.x = a0.x + a1.x; u4.y = a0.y + a1.y; u4.z = a0.z + a1.z; u4.w = a0.w + a1.w;
        v4.x = c0.x + c1.x; v4.y = c0.y + c1.y; v4.z = c0.z + c1.z; v4.w = c0.w + c1.w;
    }
    ((float4*)u)[t] = u4;
    ((float4*)v)[t] = v4;

    float lu  = u4.x + u4.y + u4.z + u4.w;
    float lv  = v4.x + v4.y + v4.z + v4.w;
    float luu = u4.x * u4.x + u4.y * u4.y + u4.z * u4.z + u4.w * u4.w;
    float lvv = v4.x * v4.x + v4.y * v4.y + v4.z * v4.z + v4.w * v4.w;
    float luv = u4.x * v4.x + u4.y * v4.y + u4.z * v4.z + u4.w * v4.w;
#pragma unroll
    for (int sft = 16; sft > 0; sft >>= 1) {
        lu  += __shfl_xor_sync(0xffffffffu, lu, sft);
        lv  += __shfl_xor_sync(0xffffffffu, lv, sft);
        luu += __shfl_xor_sync(0xffffffffu, luu, sft);
        lvv += __shfl_xor_sync(0xffffffffu, lvv, sft);
        luv += __shfl_xor_sync(0xffffffffu, luv, sft);
    }
    int lane = t & 31, wrp = t >> 5;
    if (lane == 0) {
        red[wrp][0] = lu; red[wrp][1] = lv; red[wrp][2] = luu;
        red[wrp][3] = lvv; red[wrp][4] = luv;
    }
    __syncthreads();
    float Su  = red[0][0] + red[1][0] + red[2][0] + red[3][0];
    float Sv  = red[0][1] + red[1][1] + red[2][1] + red[3][1];
    float Suu = red[0][2] + red[1][2] + red[2][2] + red[3][2];
    float Svv = red[0][3] + red[1][3] + red[2][3] + red[3][3];
    float Suv = red[0][4] + red[1][4] + red[2][4] + red[3][4];

    {
        int i = r0 + t;
        size_t off1 = (size_t)NPAIR * D;
        float iv0 = g_iv[(size_t)(2 * b) * D + i]     + g_iv[off1 + (size_t)(2 * b) * D + i];
        float iv1 = g_iv[(size_t)(2 * b + 1) * D + i] + g_iv[off1 + (size_t)(2 * b + 1) * D + i];
        float dv0 = g_dv[(size_t)(2 * b) * D + i]     + g_dv[off1 + (size_t)(2 * b) * D + i];
        float dv1 = g_dv[(size_t)(2 * b + 1) * D + i] + g_dv[off1 + (size_t)(2 * b + 1) * D + i];
        float wp0 = wp[2 * b], wp1 = wp[2 * b + 1];
        float p = wp0 * iv0;
        float q = wp1 * iv1;
        float g = wp0 * dv0 + wp1 * dv1;
        const float invD = 1.0f / (float)D;
        float mean = (p * Su + q * Sv + g) * invD;
        float ex2  = (p * p * Suu + 2.0f * p * q * Suv + q * q * Svv
                      + 2.0f * g * (p * u[i] + q * v[i]) + g * g) * invD;
        float var  = ex2 - mean * mean;
        float rstd = rsqrtf(var + 1e-5f);
        float4 pr;
        pr.x = p * rstd;
        pr.y = q * rstd;
        pr.z = -mean * rstd;
        pr.w = g * rstd;
        sparams[t] = pr;
    }
    __syncthreads();

    float* orow = outp + ((size_t)b * D + r0) * D + (t << 2);

    if (wrp == blockIdx.x) {
        int base = t << 2;
#pragma unroll 4
        for (int r = 0; r < 128; r++) {
            float4 P = sparams[r];
            float4 o;
            o.x = fmaf(P.y, v4.x, fmaf(P.x, u4.x, P.z));
            o.y = fmaf(P.y, v4.y, fmaf(P.x, u4.y, P.z));
            o.z = fmaf(P.y, v4.z, fmaf(P.x, u4.z, P.z));
            o.w = fmaf(P.y, v4.w, fmaf(P.x, u4.w, P.z));
            int dj = (r0 + r) - base;
            if (dj == 0) o.x += P.w;
            if (dj == 1) o.y += P.w;
            if (dj == 2) o.z += P.w;
            if (dj == 3) o.w += P.w;
            *(float4*)(orow + (size_t)r * D) = o;
        }
    } else {
#pragma unroll 4
        for (int r = 0; r < 128; r++) {
            float4 P = sparams[r];
            float4 o;
            o.x = fmaf(P.y, v4.x, fmaf(P.x, u4.x, P.z));
            o.y = fmaf(P.y, v4.y, fmaf(P.x, u4.y, P.z));
            o.z = fmaf(P.y, v4.z, fmaf(P.x, u4.z, P.z));
            o.w = fmaf(P.y, v4.w, fmaf(P.x, u4.w, P.z));
            *(float4*)(orow + (size_t)r * D) = o;
        }
    }

    // bmix (row-tile 0 only): bmix[b,:] = bp0*sum(bv0) + bp1*sum(bv1)
    if (blockIdx.x == 0) {
        float bp0 = bp[2 * b], bp1 = bp[2 * b + 1];
        size_t off1 = (size_t)NPAIR * D;
        float4 a0 = ((const float4*)(g_bv + (size_t)(2 * b) * D))[t];
        float4 a1 = ((const float4*)(g_bv + off1 + (size_t)(2 * b) * D))[t];
        float4 c0 = ((const float4*)(g_bv + (size_t)(2 * b + 1) * D))[t];
        float4 c1 = ((const float4*)(g_bv + off1 + (size_t)(2 * b + 1) * D))[t];
        float4 o;
        o.x = bp0 * (a0.x + a1.x) + bp1 * (c0.x + c1.x);
        o.y = bp0 * (a0.y + a1.y) + bp1 * (c0.y + c1.y);
        o.z = bp0 * (a0.z + a1.z) + bp1 * (c0.z + c1.z);
        o.w = bp0 * (a0.w + a1.w) + bp1 * (c0.w + c1.w);
        ((float4*)(outp + (size_t)BATCH * D * D + (size_t)b * D))[t] = o;
    }
}

// ---------------- launch ----------------
extern "C" void kernel_launch(void* const* d_in, const int* in_sizes, int n_in,
                              void* d_out, int out_size) {
    const float* x    = (const float*)d_in[0];
    const float* wp   = (const float*)d_in[1];
    const float* bpr  = (const float*)d_in[2];
    const float* iw   = (const float*)d_in[3];
    const float* ow   = (const float*)d_in[4];
    const float* dw   = (const float*)d_in[5];
    const float* bb   = (const float*)d_in[6];
    const int*   widx = (const int*)d_in[7];
    const int*   bidx = (const int*)d_in[8];
    float* outp = (float*)d_out;

    sort_kernel<<<1, NPAIR>>>(widx, bidx);
    gemm_kernel<<<dim3(4, MAXCH, 4 * NKS), 128>>>(x, iw, ow, dw, bb);
    mix_ln_kernel<<<dim3(4, BATCH), 128>>>(wp, bpr, outp);
}

// round 14
// speedup vs baseline: 1.0958x; 1.0958x over previous
#include <cuda_runtime.h>
#include <cstdint>

#define D      512
#define BATCH  256
#define TOPK   2
#define NEXP   16
#define NPAIR  (BATCH * TOPK)
#define MAXCH  32          // worst-case sum ceil(M_e/32) over 16 experts = 31
#define ROWS_C 32          // rows per chunk
#define KT     128         // k-tile staged in smem
#define XSTR   132         // floats per row in xs: 132 mod 32 == 4 -> frag loads conflict-free

// ---------------- scratch ----------------
__device__ float g_iv[NPAIR * D];
__device__ float g_ov[NPAIR * D];
__device__ float g_dv[NPAIR * D];
__device__ float g_bv[NPAIR * D];
__device__ int   g_list_w[NPAIR];
__device__ int   g_list_b[NPAIR];
__device__ int   g_chunks_w[MAXCH];   // packed: start | e<<16 | rows<<24
__device__ int   g_chunks_b[MAXCH];
__device__ int   g_nch_w, g_nch_b;

// ---------------- kernel 0: counting sort + 32-row chunk work-list ----------------
__global__ void sort_kernel(const int* __restrict__ widx, const int* __restrict__ bidx) {
    __shared__ int cw[NEXP], cb[NEXP], offw[NEXP + 1], offb[NEXP + 1], pw[NEXP], pb[NEXP];
    int t = threadIdx.x;                       // 512 threads == pair id
    if (t < NEXP) { cw[t] = 0; cb[t] = 0; }
    __syncthreads();
    int ew = widx[t];
    int eb = bidx[t];
    atomicAdd(&cw[ew], 1);
    atomicAdd(&cb[eb], 1);
    __syncthreads();
    if (t == 0) {
        int s = 0;
        for (int e = 0; e < NEXP; e++) { offw[e] = s; s += cw[e]; }
        offw[NEXP] = s;
        int n = 0;
        for (int e = 0; e < NEXP; e++)
            for (int c = offw[e]; c < offw[e + 1]; c += ROWS_C) {
                int rows = min(ROWS_C, offw[e + 1] - c);
                g_chunks_w[n++] = c | (e << 16) | (rows << 24);
            }
        g_nch_w = n;
    }
    if (t == 32) {
        int s = 0;
        for (int e = 0; e < NEXP; e++) { offb[e] = s; s += cb[e]; }
        offb[NEXP] = s;
        int n = 0;
        for (int e = 0; e < NEXP; e++)
            for (int c = offb[e]; c < offb[e + 1]; c += ROWS_C) {
                int rows = min(ROWS_C, offb[e + 1] - c);
                g_chunks_b[n++] = c | (e << 16) | (rows << 24);
            }
        g_nch_b = n;
    }
    __syncthreads();
    if (t < NEXP) { pw[t] = offw[t]; pb[t] = offb[t]; }
    __syncthreads();
    int posw = atomicAdd(&pw[ew], 1);
    g_list_w[posw] = t;
    int posb = atomicAdd(&pb[eb], 1);
    g_list_b[posb] = t;
}

// ---------------- tf32 helpers ----------------
__device__ __forceinline__ uint32_t f2tf32(float f) {
    uint32_t r;
    asm("cvt.rna.tf32.f32 %0, %1;" : "=r"(r) : "f"(f));
    return r;
}
__device__ __forceinline__ void mma_tf32(float* d, const uint32_t* a, const uint32_t* b) {
    asm volatile(
        "mma.sync.aligned.m16n8k8.row.col.f32.tf32.tf32.f32 "
        "{%0,%1,%2,%3}, {%4,%5,%6,%7}, {%8,%9}, {%0,%1,%2,%3};"
        : "+f"(d[0]), "+f"(d[1]), "+f"(d[2]), "+f"(d[3])
        : "r"(a[0]), "r"(a[1]), "r"(a[2]), "r"(a[3]), "r"(b[0]), "r"(b[1]));
}

// ---------------- kernel 1: grouped GEMM via tensor cores (tf32 mma.sync) ----------
// grid = (4 col-tiles of 128, MAXCH chunks, 4 banks), block = 128 threads (4 warps).
// Warp w: rows 0..31 (2 x m16) x cols [32w, 32w+32) (4 x n8), K=512 in 4 staged
// 128-k tiles. A frags from smem (tf32 bits, stride-132 => conflict-free);
// B frags direct from gmem (4 full 32B sectors per load instruction) + cvt.rna.
__global__ __launch_bounds__(128) void gemm_kernel(
    const float* __restrict__ x,
    const float* __restrict__ iw, const float* __restrict__ ow,
    const float* __restrict__ dw, const float* __restrict__ bb) {

    int bank = blockIdx.z;
    bool isW = bank < 3;
    int nch = isW ? g_nch_w : g_nch_b;
    if ((int)blockIdx.y >= nch) return;

    __shared__ __align__(16) uint32_t xs[ROWS_C * XSTR];   // 16.9KB tf32 bits

    int packed = (isW ? g_chunks_w : g_chunks_b)[blockIdx.y];
    int s    = packed & 0xFFFF;
    int e    = (packed >> 16) & 0xFF;
    int rows = (packed >> 24) & 0xFF;

    const int* list = isW ? g_list_w : g_list_b;
    const float* W  = ((bank == 0) ? iw : (bank == 1) ? ow : (bank == 2) ? dw : bb)
                      + (size_t)e * D * D;
    float* out = (bank == 0) ? g_iv : (bank == 1) ? g_ov : (bank == 2) ? g_dv : g_bv;

    int t    = threadIdx.x;
    int lane = t & 31;
    int wid  = t >> 5;
    int grp  = lane >> 2;     // 0..7
    int tg   = lane & 3;      // 0..3
    int col0w = blockIdx.x * 128 + wid * 32;

    float d[2][4][4];
#pragma unroll
    for (int tm = 0; tm < 2; tm++)
#pragma unroll
        for (int tn = 0; tn < 4; tn++)
#pragma unroll
            for (int r = 0; r < 4; r++) d[tm][tn][r] = 0.0f;

    for (int kt = 0; kt < D / KT; kt++) {
        int kglob0 = kt * KT;
        __syncthreads();   // previous tile's frag reads done before restage
        // stage x tile [32 rows x 128 k] as tf32 bits (coalesced: k = t)
#pragma unroll 4
        for (int i = 0; i < ROWS_C; i++) {
            float val = 0.0f;
            if (i < rows) val = x[(list[s + i] >> 1) * D + kglob0 + t];
            xs[i * XSTR + t] = f2tf32(val);
        }
        __syncthreads();

        // W rows for this thread's B frags: k = kglob0 + tg (+kb, +4)
        const float* Wk = W + (size_t)(kglob0 + tg) * D + col0w + grp;

#pragma unroll 4
        for (int k8 = 0; k8 < KT / 8; k8++) {
            int kb = k8 * 8;
            // A fragments (tf32 bits from smem)
            uint32_t a[2][4];
#pragma unroll
            for (int tm = 0; tm < 2; tm++) {
                int rbase = tm * 16 + grp;
                a[tm][0] = xs[(rbase)      * XSTR + kb + tg];
                a[tm][1] = xs[(rbase + 8)  * XSTR + kb + tg];
                a[tm][2] = xs[(rbase)      * XSTR + kb + tg + 4];
                a[tm][3] = xs[(rbase + 8)  * XSTR + kb + tg + 4];
            }
            // B fragments (direct gmem + cvt)
            uint32_t b[4][2];
#pragma unroll
            for (int tn = 0; tn < 4; tn++) {
                float b0 = Wk[(size_t)kb * D + tn * 8];
                float b1 = Wk[(size_t)(kb + 4) * D + tn * 8];
                b[tn][0] = f2tf32(b0);
                b[tn][1] = f2tf32(b1);
            }
            // 8 MMAs
#pragma unroll
            for (int tm = 0; tm < 2; tm++)
#pragma unroll
                for (int tn = 0; tn < 4; tn++)
                    mma_tf32(d[tm][tn], a[tm], b[tn]);
        }
    }

    // store: d[tm][tn] covers rows {tm*16+grp, +8} x cols {col0w+tn*8+tg*2, +1}
#pragma unroll
    for (int tm = 0; tm < 2; tm++) {
#pragma unroll
        for (int tn = 0; tn < 4; tn++) {
            int col = col0w + tn * 8 + tg * 2;
            int row0 = tm * 16 + grp;
            int row1 = row0 + 8;
            if (row0 < rows) {
                float2 v = make_float2(d[tm][tn][0], d[tm][tn][1]);
                *(float2*)&out[(size_t)list[s + row0] * D + col] = v;
            }
            if (row1 < rows) {
                float2 v = make_float2(d[tm][tn][2], d[tm][tn][3]);
                *(float2*)&out[(size_t)list[s + row1] * D + col] = v;
            }
        }
    }
}

// ---------------- kernel 2: rank-2 mix + analytic LayerNorm + bmix (r5-exact) ------
__global__ __launch_bounds__(128) void mix_ln_kernel(
    const float* __restrict__ wp, const float* __restrict__ bp,
    float* __restrict__ outp) {

    int b  = blockIdx.y;
    int r0 = blockIdx.x * 128;
    int t  = threadIdx.x;

    __shared__ float u[D], v[D];
    __shared__ __align__(16) float4 sparams[128];   // {pr, qr, c, gr}
    __shared__ float red[4][5];

    const float* u_g = g_ov + (size_t)(2 * b) * D;
    const float* v_g = g_ov + (size_t)(2 * b + 1) * D;
    float4 u4 = ((const float4*)u_g)[t];
    float4 v4 = ((const float4*)v_g)[t];
    ((float4*)u)[t] = u4;
    ((float4*)v)[t] = v4;

    float lu  = u4.x + u4.y + u4.z + u4.w;
    float lv  = v4.x + v4.y + v4.z + v4.w;
    float luu = u4.x * u4.x + u4.y * u4.y + u4.z * u4.z + u4.w * u4.w;
    float lvv = v4.x * v4.x + v4.y * v4.y + v4.z * v4.z + v4.w * v4.w;
    float luv = u4.x * v4.x + u4.y * v4.y + u4.z * v4.z + u4.w * v4.w;
#pragma unroll
    for (int sft = 16; sft > 0; sft >>= 1) {
        lu  += __shfl_xor_sync(0xffffffffu, lu, sft);
        lv  += __shfl_xor_sync(0xffffffffu, lv, sft);
        luu += __shfl_xor_sync(0xffffffffu, luu, sft);
        lvv += __shfl_xor_sync(0xffffffffu, lvv, sft);
        luv += __shfl_xor_sync(0xffffffffu, luv, sft);
    }
    int lane = t & 31, wrp = t >> 5;
    if (lane == 0) {
        red[wrp][0] = lu; red[wrp][1] = lv; red[wrp][2] = luu;
        red[wrp][3] = lvv; red[wrp][4] = luv;
    }
    __syncthreads();
    float Su  = red[0][0] + red[1][0] + red[2][0] + red[3][0];
    float Sv  = red[0][1] + red[1][1] + red[2][1] + red[3][1];
    float Suu = red[0][2] + red[1][2] + red[2][2] + red[3][2];
    float Svv = red[0][3] + red[1][3] + red[2][3] + red[3][3];
    float Suv = red[0][4] + red[1][4] + red[2][4] + red[3][4];

    {
        int i = r0 + t;
        float wp0 = wp[2 * b], wp1 = wp[2 * b + 1];
        float p = wp0 * g_iv[(size_t)(2 * b) * D + i];
        float q = wp1 * g_iv[(size_t)(2 * b + 1) * D + i];
        float g = wp0 * g_dv[(size_t)(2 * b) * D + i]
                + wp1 * g_dv[(size_t)(2 * b + 1) * D + i];
        const float invD = 1.0f / (float)D;
        float mean = (p * Su + q * Sv + g) * invD;
        float ex2  = (p * p * Suu + 2.0f * p * q * Suv + q * q * Svv
                      + 2.0f * g * (p * u[i] + q * v[i]) + g * g) * invD;
        float var  = ex2 - mean * mean;
        float rstd = rsqrtf(var + 1e-5f);
        float4 pr;
        pr.x = p * rstd;
        pr.y = q * rstd;
        pr.z = -mean * rstd;
        pr.w = g * rstd;
        sparams[t] = pr;
    }
    __syncthreads();

    float* orow = outp + ((size_t)b * D + r0) * D + (t << 2);

    if (wrp == blockIdx.x) {
        int base = t << 2;
#pragma unroll 4
        for (int r = 0; r < 128; r++) {
            float4 P = sparams[r];
            float4 o;
            o.x = fmaf(P.y, v4.x, fmaf(P.x, u4.x, P.z));
            o.y = fmaf(P.y, v4.y, fmaf(P.x, u4.y, P.z));
            o.z = fmaf(P.y, v4.z, fmaf(P.x, u4.z, P.z));
            o.w = fmaf(P.y, v4.w, fmaf(P.x, u4.w, P.z));
            int dj = (r0 + r) - base;
            if (dj == 0) o.x += P.w;
            if (dj == 1) o.y += P.w;
            if (dj == 2) o.z += P.w;
            if (dj == 3) o.w += P.w;
            *(float4*)(orow + (size_t)r * D) = o;
        }
    } else {
#pragma unroll 4
        for (int r = 0; r < 128; r++) {
            float4 P = sparams[r];
            float4 o;
            o.x = fmaf(P.y, v4.x, fmaf(P.x, u4.x, P.z));
            o.y = fmaf(P.y, v4.y, fmaf(P.x, u4.y, P.z));
            o.z = fmaf(P.y, v4.z, fmaf(P.x, u4.z, P.z));
            o.w = fmaf(P.y, v4.w, fmaf(P.x, u4.w, P.z));
            *(float4*)(orow + (size_t)r * D) = o;
        }
    }

    // bmix (row-tile 0 only): bmix[b,:] = bp0*bv0 + bp1*bv1
    if (blockIdx.x == 0) {
        float bp0 = bp[2 * b], bp1 = bp[2 * b + 1];
        float4 b0 = ((const float4*)(g_bv + (size_t)(2 * b) * D))[t];
        float4 b1 = ((const float4*)(g_bv + (size_t)(2 * b + 1) * D))[t];
        float4 o;
        o.x = bp0 * b0.x + bp1 * b1.x;
        o.y = bp0 * b0.y + bp1 * b1.y;
        o.z = bp0 * b0.z + bp1 * b1.z;
        o.w = bp0 * b0.w + bp1 * b1.w;
        ((float4*)(outp + (size_t)BATCH * D * D + (size_t)b * D))[t] = o;
    }
}

// ---------------- launch ----------------
extern "C" void kernel_launch(void* const* d_in, const int* in_sizes, int n_in,
                              void* d_out, int out_size) {
    const float* x    = (const float*)d_in[0];
    const float* wp   = (const float*)d_in[1];
    const float* bpr  = (const float*)d_in[2];
    const float* iw   = (const float*)d_in[3];
    const float* ow   = (const float*)d_in[4];
    const float* dw   = (const float*)d_in[5];
    const float* bb   = (const float*)d_in[6];
    const int*   widx = (const int*)d_in[7];
    const int*   bidx = (const int*)d_in[8];
    float* outp = (float*)d_out;

    sort_kernel<<<1, NPAIR>>>(widx, bidx);
    gemm_kernel<<<dim3(4, MAXCH, 4), 128>>>(x, iw, ow, dw, bb);
    mix_ln_kernel<<<dim3(4, BATCH), 128>>>(wp, bpr, outp);
}

// round 15
// speedup vs baseline: 1.3226x; 1.2069x over previous
#include <cuda_runtime.h>
#include <cstdint>

#define D      512
#define BATCH  256
#define TOPK   2
#define NEXP   16
#define NPAIR  (BATCH * TOPK)
#define MAXCH  32          // worst-case sum ceil(M_e/32) over 16 experts = 31
#define ROWS_C 32          // rows per chunk
#define NKS    2           // k-splits
#define KSL    (D / NKS)   // 256 kk per split
#define KT     128         // k-tile staged in smem
#define XSTR   132         // uint32 per row in xs: 132 mod 32 == 4 -> conflict-free frags

// ---------------- scratch (per-split partial buffers) ----------------
__device__ float g_iv[NKS * NPAIR * D];
__device__ float g_ov[NKS * NPAIR * D];
__device__ float g_dv[NKS * NPAIR * D];
__device__ float g_bv[NKS * NPAIR * D];
__device__ int   g_list_w[NPAIR];
__device__ int   g_list_b[NPAIR];
__device__ int   g_chunks_w[MAXCH];   // packed: start | e<<16 | rows<<24
__device__ int   g_chunks_b[MAXCH];
__device__ int   g_nch_w, g_nch_b;

// ---------------- kernel 0: counting sort + 32-row chunk work-list ----------------
__global__ void sort_kernel(const int* __restrict__ widx, const int* __restrict__ bidx) {
    __shared__ int cw[NEXP], cb[NEXP], offw[NEXP + 1], offb[NEXP + 1], pw[NEXP], pb[NEXP];
    int t = threadIdx.x;                       // 512 threads == pair id
    if (t < NEXP) { cw[t] = 0; cb[t] = 0; }
    __syncthreads();
    int ew = widx[t];
    int eb = bidx[t];
    atomicAdd(&cw[ew], 1);
    atomicAdd(&cb[eb], 1);
    __syncthreads();
    if (t == 0) {
        int s = 0;
        for (int e = 0; e < NEXP; e++) { offw[e] = s; s += cw[e]; }
        offw[NEXP] = s;
        int n = 0;
        for (int e = 0; e < NEXP; e++)
            for (int c = offw[e]; c < offw[e + 1]; c += ROWS_C) {
                int rows = min(ROWS_C, offw[e + 1] - c);
                g_chunks_w[n++] = c | (e << 16) | (rows << 24);
            }
        g_nch_w = n;
    }
    if (t == 32) {
        int s = 0;
        for (int e = 0; e < NEXP; e++) { offb[e] = s; s += cb[e]; }
        offb[NEXP] = s;
        int n = 0;
        for (int e = 0; e < NEXP; e++)
            for (int c = offb[e]; c < offb[e + 1]; c += ROWS_C) {
                int rows = min(ROWS_C, offb[e + 1] - c);
                g_chunks_b[n++] = c | (e << 16) | (rows << 24);
            }
        g_nch_b = n;
    }
    __syncthreads();
    if (t < NEXP) { pw[t] = offw[t]; pb[t] = offb[t]; }
    __syncthreads();
    int posw = atomicAdd(&pw[ew], 1);
    g_list_w[posw] = t;
    int posb = atomicAdd(&pb[eb], 1);
    g_list_b[posb] = t;
}

// ---------------- tf32 helpers ----------------
__device__ __forceinline__ uint32_t f2tf32(float f) {
    uint32_t r;
    asm("cvt.rna.tf32.f32 %0, %1;" : "=r"(r) : "f"(f));
    return r;
}
__device__ __forceinline__ void mma_tf32(float* d, const uint32_t* a, const uint32_t* b) {
    asm volatile(
        "mma.sync.aligned.m16n8k8.row.col.f32.tf32.tf32.f32 "
        "{%0,%1,%2,%3}, {%4,%5,%6,%7}, {%8,%9}, {%0,%1,%2,%3};"
        : "+f"(d[0]), "+f"(d[1]), "+f"(d[2]), "+f"(d[3])
        : "r"(a[0]), "r"(a[1]), "r"(a[2]), "r"(a[3]), "r"(b[0]), "r"(b[1]));
}

// ---------------- kernel 1: grouped GEMM via tf32 mma.sync + split-K=2 -------------
// grid = (4 col-tiles of 128, MAXCH chunks, 4 banks * 2 ksplits), block = 128 (4 warps).
// Warp w: rows 0..31 (2 x m16) x cols [32w, 32w+32) (4 x n8); each block covers
// K in [ks*256, ks*256+256) as 2 staged 128-k tiles; partials go to split buffers.
// A frags from smem (tf32 bits, stride-132 conflict-free); B frags direct from gmem
// (4 full 32B sectors per load instr) + cvt.rna. Split-K doubles resident warps.
__global__ __launch_bounds__(128) void gemm_kernel(
    const float* __restrict__ x,
    const float* __restrict__ iw, const float* __restrict__ ow,
    const float* __restrict__ dw, const float* __restrict__ bb) {

    int z    = blockIdx.z;
    int bank = z & 3;
    int ks   = z >> 2;
    bool isW = bank < 3;
    int nch = isW ? g_nch_w : g_nch_b;
    if ((int)blockIdx.y >= nch) return;

    __shared__ __align__(16) uint32_t xs[ROWS_C * XSTR];   // 16.9KB tf32 bits

    int packed = (isW ? g_chunks_w : g_chunks_b)[blockIdx.y];
    int s    = packed & 0xFFFF;
    int e    = (packed >> 16) & 0xFF;
    int rows = (packed >> 24) & 0xFF;

    const int* list = isW ? g_list_w : g_list_b;
    const float* W  = ((bank == 0) ? iw : (bank == 1) ? ow : (bank == 2) ? dw : bb)
                      + (size_t)e * D * D;
    float* out = ((bank == 0) ? g_iv : (bank == 1) ? g_ov : (bank == 2) ? g_dv : g_bv)
                 + (size_t)ks * NPAIR * D;

    int t    = threadIdx.x;
    int lane = t & 31;
    int wid  = t >> 5;
    int grp  = lane >> 2;     // 0..7
    int tg   = lane & 3;      // 0..3
    int col0w = blockIdx.x * 128 + wid * 32;

    float d[2][4][4];
#pragma unroll
    for (int tm = 0; tm < 2; tm++)
#pragma unroll
        for (int tn = 0; tn < 4; tn++)
#pragma unroll
            for (int r = 0; r < 4; r++) d[tm][tn][r] = 0.0f;

    for (int kt = 0; kt < KSL / KT; kt++) {
        int kglob0 = ks * KSL + kt * KT;
        __syncthreads();   // previous tile's frag reads done before restage
        // stage x tile [32 rows x 128 k] as tf32 bits (coalesced: k = t)
#pragma unroll 4
        for (int i = 0; i < ROWS_C; i++) {
            float val = 0.0f;
            if (i < rows) val = x[(list[s + i] >> 1) * D + kglob0 + t];
            xs[i * XSTR + t] = f2tf32(val);
        }
        __syncthreads();

        // W rows for this thread's B frags: k = kglob0 + tg (+kb, +4)
        const float* Wk = W + (size_t)(kglob0 + tg) * D + col0w + grp;

#pragma unroll 4
        for (int k8 = 0; k8 < KT / 8; k8++) {
            int kb = k8 * 8;
            // A fragments (tf32 bits from smem)
            uint32_t a[2][4];
#pragma unroll
            for (int tm = 0; tm < 2; tm++) {
                int rbase = tm * 16 + grp;
                a[tm][0] = xs[(rbase)      * XSTR + kb + tg];
                a[tm][1] = xs[(rbase + 8)  * XSTR + kb + tg];
                a[tm][2] = xs[(rbase)      * XSTR + kb + tg + 4];
                a[tm][3] = xs[(rbase + 8)  * XSTR + kb + tg + 4];
            }
            // B fragments (direct gmem + cvt)
            uint32_t b[4][2];
#pragma unroll
            for (int tn = 0; tn < 4; tn++) {
                float b0 = Wk[(size_t)kb * D + tn * 8];
                float b1 = Wk[(size_t)(kb + 4) * D + tn * 8];
                b[tn][0] = f2tf32(b0);
                b[tn][1] = f2tf32(b1);
            }
            // 8 MMAs
#pragma unroll
            for (int tm = 0; tm < 2; tm++)
#pragma unroll
                for (int tn = 0; tn < 4; tn++)
                    mma_tf32(d[tm][tn], a[tm], b[tn]);
        }
    }

    // store: d[tm][tn] covers rows {tm*16+grp, +8} x cols {col0w+tn*8+tg*2, +1}
#pragma unroll
    for (int tm = 0; tm < 2; tm++) {
#pragma unroll
        for (int tn = 0; tn < 4; tn++) {
            int col = col0w + tn * 8 + tg * 2;
            int row0 = tm * 16 + grp;
            int row1 = row0 + 8;
            if (row0 < rows) {
                float2 v = make_float2(d[tm][tn][0], d[tm][tn][1]);
                *(float2*)&out[(size_t)list[s + row0] * D + col] = v;
            }
            if (row1 < rows) {
                float2 v = make_float2(d[tm][tn][2], d[tm][tn][3]);
                *(float2*)&out[(size_t)list[s + row1] * D + col] = v;
            }
        }
    }
}

// ---------------- kernel 2: sum 2 k-splits + rank-2 mix + analytic LN + bmix -------
__global__ __launch_bounds__(128) void mix_ln_kernel(
    const float* __restrict__ wp, const float* __restrict__ bp,
    float* __restrict__ outp) {

    int b  = blockIdx.y;
    int r0 = blockIdx.x * 128;
    int t  = threadIdx.x;

    __shared__ float u[D], v[D];
    __shared__ __align__(16) float4 sparams[128];   // {pr, qr, c, gr}
    __shared__ float red[4][5];

    float4 u4, v4;
    {
        const float* b0p = g_ov;
        const float* b1p = g_ov + (size_t)NPAIR * D;
        float4 a0 = ((const float4*)(b0p + (size_t)(2 * b) * D))[t];
        float4 a1 = ((const float4*)(b1p + (size_t)(2 * b) * D))[t];
        float4 c0 = ((const float4*)(b0p + (size_t)(2 * b + 1) * D))[t];
        float4 c1 = ((const float4*)(b1p + (size_t)(2 * b + 1) * D))[t];
        u4.x = a0.x + a1.x; u4.y = a0.y + a1.y; u4.z = a0.z + a1.z; u4.w = a0.w + a1.w;
        v4.x = c0.x + c1.x; v4.y = c0.y + c1.y; v4.z = c0.z + c1.z; v4.w = c0.w + c1.w;
    }
    ((float4*)u)[t] = u4;
    ((float4*)v)[t] = v4;

    float lu  = u4.x + u4.y + u4.z + u4.w;
    float lv  = v4.x + v4.y + v4.z + v4.w;
    float luu = u4.x * u4.x + u4.y * u4.y + u4.z * u4.z + u4.w * u4.w;
    float lvv = v4.x * v4.x + v4.y * v4.y + v4.z * v4.z + v4.w * v4.w;
    float luv = u4.x * v4.x + u4.y * v4.y + u4.z * v4.z + u4.w * v4.w;
#pragma unroll
    for (int sft = 16; sft > 0; sft >>= 1) {
        lu  += __shfl_xor_sync(0xffffffffu, lu, sft);
        lv  += __shfl_xor_sync(0xffffffffu, lv, sft);
        luu += __shfl_xor_sync(0xffffffffu, luu, sft);
        lvv += __shfl_xor_sync(0xffffffffu, lvv, sft);
        luv += __shfl_xor_sync(0xffffffffu, luv, sft);
    }
    int lane = t & 31, wrp = t >> 5;
    if (lane == 0) {
        red[wrp][0] = lu; red[wrp][1] = lv; red[wrp][2] = luu;
        red[wrp][3] = lvv; red[wrp][4] = luv;
    }
    __syncthreads();
    float Su  = red[0][0] + red[1][0] + red[2][0] + red[3][0];
    float Sv  = red[0][1] + red[1][1] + red[2][1] + red[3][1];
    float Suu = red[0][2] + red[1][2] + red[2][2] + red[3][2];
    float Svv = red[0][3] + red[1][3] + red[2][3] + red[3][3];
    float Suv = red[0][4] + red[1][4] + red[2][4] + red[3][4];

    {
        int i = r0 + t;
        size_t off1 = (size_t)NPAIR * D;
        float iv0 = g_iv[(size_t)(2 * b) * D + i]     + g_iv[off1 + (size_t)(2 * b) * D + i];
        float iv1 = g_iv[(size_t)(2 * b + 1) * D + i] + g_iv[off1 + (size_t)(2 * b + 1) * D + i];
        float dv0 = g_dv[(size_t)(2 * b) * D + i]     + g_dv[off1 + (size_t)(2 * b) * D + i];
        float dv1 = g_dv[(size_t)(2 * b + 1) * D + i] + g_dv[off1 + (size_t)(2 * b + 1) * D + i];
        float wp0 = wp[2 * b], wp1 = wp[2 * b + 1];
        float p = wp0 * iv0;
        float q = wp1 * iv1;
        float g = wp0 * dv0 + wp1 * dv1;
        const float invD = 1.0f / (float)D;
        float mean = (p * Su + q * Sv + g) * invD;
        float ex2  = (p * p * Suu + 2.0f * p * q * Suv + q * q * Svv
                      + 2.0f * g * (p * u[i] + q * v[i]) + g * g) * invD;
        float var  = ex2 - mean * mean;
        float rstd = rsqrtf(var + 1e-5f);
        float4 pr;
        pr.x = p * rstd;
        pr.y = q * rstd;
        pr.z = -mean * rstd;
        pr.w = g * rstd;
        sparams[t] = pr;
    }
    __syncthreads();

    float* orow = outp + ((size_t)b * D + r0) * D + (t << 2);

    if (wrp == blockIdx.x) {
        int base = t << 2;
#pragma unroll 4
        for (int r = 0; r < 128; r++) {
            float4 P = sparams[r];
            float4 o;
            o.x = fmaf(P.y, v4.x, fmaf(P.x, u4.x, P.z));
            o.y = fmaf(P.y, v4.y, fmaf(P.x, u4.y, P.z));
            o.z = fmaf(P.y, v4.z, fmaf(P.x, u4.z, P.z));
            o.w = fmaf(P.y, v4.w, fmaf(P.x, u4.w, P.z));
            int dj = (r0 + r) - base;
            if (dj == 0) o.x += P.w;
            if (dj == 1) o.y += P.w;
            if (dj == 2) o.z += P.w;
            if (dj == 3) o.w += P.w;
            *(float4*)(orow + (size_t)r * D) = o;
        }
    } else {
#pragma unroll 4
        for (int r = 0; r < 128; r++) {
            float4 P = sparams[r];
            float4 o;
            o.x = fmaf(P.y, v4.x, fmaf(P.x, u4.x, P.z));
            o.y = fmaf(P.y, v4.y, fmaf(P.x, u4.y, P.z));
            o.z = fmaf(P.y, v4.z, fmaf(P.x, u4.z, P.z));
            o.w = fmaf(P.y, v4.w, fmaf(P.x, u4.w, P.z));
            *(float4*)(orow + (size_t)r * D) = o;
        }
    }

    // bmix (row-tile 0 only): bmix[b,:] = bp0*sum(bv0) + bp1*sum(bv1)
    if (blockIdx.x == 0) {
        float bp0 = bp[2 * b], bp1 = bp[2 * b + 1];
        size_t off1 = (size_t)NPAIR * D;
        float4 a0 = ((const float4*)(g_bv + (size_t)(2 * b) * D))[t];
        float4 a1 = ((const float4*)(g_bv + off1 + (size_t)(2 * b) * D))[t];
        float4 c0 = ((const float4*)(g_bv + (size_t)(2 * b + 1) * D))[t];
        float4 c1 = ((const float4*)(g_bv + off1 + (size_t)(2 * b + 1) * D))[t];
        float4 o;
        o.x = bp0 * (a0.x + a1.x) + bp1 * (c0.x + c1.x);
        o.y = bp0 * (a0.y + a1.y) + bp1 * (c0.y + c1.y);
        o.z = bp0 * (a0.z + a1.z) + bp1 * (c0.z + c1.z);
        o.w = bp0 * (a0.w + a1.w) + bp1 * (c0.w + c1.w);
        ((float4*)(outp + (size_t)BATCH * D * D + (size_t)b * D))[t] = o;
    }
}

// ---------------- launch ----------------
extern "C" void kernel_launch(void* const* d_in, const int* in_sizes, int n_in,
                              void* d_out, int out_size) {
    const float* x    = (const float*)d_in[0];
    const float* wp   = (const float*)d_in[1];
    const float* bpr  = (const float*)d_in[2];
    const float* iw   = (const float*)d_in[3];
    const float* ow   = (const float*)d_in[4];
    const float* dw   = (const float*)d_in[5];
    const float* bb   = (const float*)d_in[6];
    const int*   widx = (const int*)d_in[7];
    const int*   bidx = (const int*)d_in[8];
    float* outp = (float*)d_out;

    sort_kernel<<<1, NPAIR>>>(widx, bidx);
    gemm_kernel<<<dim3(4, MAXCH, 4 * NKS), 128>>>(x, iw, ow, dw, bb);
    mix_ln_kernel<<<dim3(4, BATCH), 128>>>(wp, bpr, outp);
}